// round 1
// baseline (speedup 1.0000x reference)
#include <cuda_runtime.h>
#include <math.h>

// Problem constants
#define S_N   256
#define V_N   200
#define F_N   5
#define G_N   80
#define NT    16     // thetas
#define NR    5      // rhos
#define NROT  16
#define RK    256    // NROT * NT
#define EPSF  1e-5f

// Scratch (static device arrays — no allocation)
__device__ float d_T[(size_t)S_N * V_N * RK];   // tg  [s][v][r*16+k]      52.4 MB
__device__ float d_A[(size_t)S_N * V_N * 32];   // [s][v][p*6+f'] pad 32    6.6 MB
__device__ float d_GDN[(size_t)S_N * RK * 25];  // [s][rk][p*5+f]           6.6 MB
__device__ float d_DESC[(size_t)S_N * 400];     // [s][f*80+g']             0.4 MB

// ---------------------------------------------------------------------------
// Kernel 1: per (s,v) point — compute radial gaussians (5, f-independent),
// angular gaussians for all 16 rotations x 16 theta-centers (256), and the
// A matrix rows rg*mask*{1, feat0..4}.
// ---------------------------------------------------------------------------
__global__ void k1_gauss(const float* __restrict__ feat,
                         const float* __restrict__ rho,
                         const float* __restrict__ theta,
                         const float* __restrict__ mask,
                         const float* __restrict__ mu_rho,
                         const float* __restrict__ sigma_rho,
                         const float* __restrict__ mu_theta,
                         const float* __restrict__ sigma_theta)
{
    __shared__ float s_mu_t[NT], s_is_t[NT], s_mu_r[NR], s_is_r[NR];
    int tid = threadIdx.x;
    if (tid < NT) {
        float mt = mu_theta[tid];           // row f=0, g = k (p=0)
        float st = sigma_theta[tid];
        s_mu_t[tid] = mt;
        s_is_t[tid] = 1.0f / (st * st + EPSF);
    }
    if (tid < NR) {
        float mr = mu_rho[tid * NT];        // row f=0, g = p*16
        float sr = sigma_rho[tid * NT];
        s_mu_r[tid] = mr;
        s_is_r[tid] = 1.0f / (sr * sr + EPSF);
    }
    __syncthreads();

    int idx = blockIdx.x * blockDim.x + tid;
    if (idx >= S_N * V_N) return;

    float t  = theta[idx];
    float rh = rho[idx];
    float m  = mask[idx];

    // A rows: [p*6 + f'], f'=0 -> rg*m, f'=1..5 -> rg*m*feat
    float fv[5];
#pragma unroll
    for (int f = 0; f < 5; f++) fv[f] = feat[idx * 5 + f];

    float a[32];
#pragma unroll
    for (int p = 0; p < NR; p++) {
        float d  = rh - s_mu_r[p];
        float rg = __expf(-d * d * s_is_r[p]);
        float rm = rg * m;
        a[p * 6] = rm;
#pragma unroll
        for (int f = 0; f < 5; f++) a[p * 6 + 1 + f] = rm * fv[f];
    }
    a[30] = 0.0f; a[31] = 0.0f;

    float4* aout = (float4*)(d_A + (size_t)idx * 32);
#pragma unroll
    for (int j = 0; j < 8; j++) aout[j] = ((float4*)a)[j];

    const float TWO_PI_F = 6.2831853071795864769f;
    const float DTH      = TWO_PI_F / 16.0f;
    float4* tout = (float4*)(d_T + (size_t)idx * RK);
#pragma unroll
    for (int r = 0; r < NROT; r++) {
        float tr = fmodf(t + (float)r * DTH, TWO_PI_F);
        float buf[16];
#pragma unroll
        for (int k = 0; k < NT; k++) {
            float d = tr - s_mu_t[k];
            buf[k] = __expf(-d * d * s_is_t[k]);
        }
#pragma unroll
        for (int j = 0; j < 4; j++) tout[r * 4 + j] = ((float4*)buf)[j];
    }
}

// ---------------------------------------------------------------------------
// Kernel 2: per-s GEMM  gd[rk][p,f'] = sum_v tg[rk][v] * A[v][p,f'],
// then normalize: GDN[rk][p*5+f] = num / (den + eps).
// Block = one s, 256 threads (one per rk). A tile cached in smem.
// ---------------------------------------------------------------------------
__global__ void k2_gemm()
{
    int s   = blockIdx.x;
    int tid = threadIdx.x;  // rk

    __shared__ float4 As[V_N * 8];  // 25.6 KB
    const float4* ag = (const float4*)(d_A + (size_t)s * V_N * 32);
    for (int i = tid; i < V_N * 8; i += 256) As[i] = ag[i];
    __syncthreads();

    float acc[32];
#pragma unroll
    for (int j = 0; j < 32; j++) acc[j] = 0.0f;

    const float* trow = d_T + (size_t)s * V_N * RK + tid;
#pragma unroll 4
    for (int v = 0; v < V_N; v++) {
        float tg = trow[(size_t)v * RK];   // coalesced across the warp
#pragma unroll
        for (int j4 = 0; j4 < 8; j4++) {
            float4 av = As[v * 8 + j4];    // broadcast
            acc[j4 * 4 + 0] += tg * av.x;
            acc[j4 * 4 + 1] += tg * av.y;
            acc[j4 * 4 + 2] += tg * av.z;
            acc[j4 * 4 + 3] += tg * av.w;
        }
    }

    float* gout = d_GDN + ((size_t)s * RK + tid) * 25;
#pragma unroll
    for (int p = 0; p < NR; p++) {
        float inv = 1.0f / (acc[p * 6] + EPSF);
#pragma unroll
        for (int f = 0; f < 5; f++) gout[p * 5 + f] = acc[p * 6 + 1 + f] * inv;
    }
}

// ---------------------------------------------------------------------------
// Kernel 3: conv GEMM + bias + max over rotations + relu.
// Block = one s, 400 threads = (f, g'). W_conv cached in smem; gd staged in
// r-chunks of 4 (keeps static smem under 48 KB).
// ---------------------------------------------------------------------------
__global__ void k3_conv(const float* __restrict__ Wc,
                        const float* __restrict__ bc)
{
    __shared__ float Wsh[G_N * G_N];      // 25.6 KB
    __shared__ float gsh[4 * G_N * F_N];  // 6.4 KB, layout [rloc][g][f]

    int s   = blockIdx.x;
    int tid = threadIdx.x;  // 0..399
    for (int i = tid; i < G_N * G_N; i += 400) Wsh[i] = Wc[i];

    int gp = tid % 80;
    int f  = tid / 80;
    float maxv = -1e30f;
    const float* gsrc = d_GDN + (size_t)s * RK * 25;

    for (int rc = 0; rc < 4; rc++) {
        __syncthreads();  // also orders the Wsh fill before first use
        // stage 4 rotations: gsh[(rloc*80 + p*16 + k)*5 + f]
        for (int i = tid; i < 4 * NT * 25; i += 400) {
            int rloc = i / (NT * 25);
            int rem  = i % (NT * 25);
            int k = rem / 25, q = rem % 25;
            int p = q / 5,  ff = q % 5;
            gsh[(rloc * 80 + p * 16 + k) * 5 + ff] =
                gsrc[((size_t)(rc * 4 + rloc) * 16 + k) * 25 + q];
        }
        __syncthreads();
#pragma unroll
        for (int rloc = 0; rloc < 4; rloc++) {
            float dot = 0.0f;
            const float* gr = &gsh[rloc * 400 + f];
#pragma unroll 8
            for (int g = 0; g < G_N; g++)
                dot += gr[g * 5] * Wsh[g * 80 + gp];
            maxv = fmaxf(maxv, dot);
        }
    }

    float val = maxv + bc[f * 80 + gp];
    d_DESC[(size_t)s * 400 + f * 80 + gp] = fmaxf(val, 0.0f);
}

// ---------------------------------------------------------------------------
// Kernel 4: fcc — global_desc[s] = desc[s] @ fcc_w + fcc_b.
// Block = one s, 80 threads.
// ---------------------------------------------------------------------------
__global__ void k4_fcc(const float* __restrict__ fw,
                       const float* __restrict__ fb,
                       float* __restrict__ out)
{
    __shared__ float drow[400];
    int s   = blockIdx.x;
    int tid = threadIdx.x;  // 0..79
    for (int i = tid; i < 400; i += 80) drow[i] = d_DESC[(size_t)s * 400 + i];
    __syncthreads();

    float acc = fb[tid];
#pragma unroll 8
    for (int j = 0; j < 400; j++)
        acc += drow[j] * fw[j * 80 + tid];   // coalesced, L2-resident
    out[(size_t)s * 80 + tid] = acc;
}

// ---------------------------------------------------------------------------
// Kernel 5: pairwise distances, score, data_loss. One block, 128 threads.
// out layout: [0:20480) global_desc, [20480] data_loss, [20481:20609) score
// ---------------------------------------------------------------------------
__global__ void k5_loss(float* __restrict__ out)
{
    int tid = threadIdx.x;  // 0..127
    const float* gd = out;
    int i = tid & 63;
    const float *xa, *xb;
    if (tid < 64) { xa = gd + (size_t)(64 + i) * 80;  xb = gd + (size_t)i * 80; }
    else          { xa = gd + (size_t)(128 + i) * 80; xb = gd + (size_t)(192 + i) * 80; }

    float d = 0.0f;
#pragma unroll 8
    for (int j = 0; j < 80; j++) {
        float df = xa[j] - xb[j];
        d += df * df;
    }
    out[20481 + tid] = d;                       // score

    __shared__ float sd[128];
    float rv = (tid < 64) ? fmaxf(d - 0.0f, 0.0f)     // pos_r
                          : fmaxf(10.0f - d, 0.0f);   // neg_r
    sd[tid] = rv;
    __syncthreads();

    if (tid == 0) {
        float mp = 0.0f, mn = 0.0f;
        for (int j = 0; j < 64; j++) { mp += sd[j]; mn += sd[64 + j]; }
        mp *= (1.0f / 64.0f); mn *= (1.0f / 64.0f);
        float vp = 0.0f, vn = 0.0f;
        for (int j = 0; j < 64; j++) {
            float a = sd[j]      - mp; vp += a * a;
            float c = sd[64 + j] - mn; vn += c * c;
        }
        out[20480] = sqrtf(vp / 63.0f) + sqrtf(vn / 63.0f) + mp + mn;
    }
}

// ---------------------------------------------------------------------------
extern "C" void kernel_launch(void* const* d_in, const int* in_sizes, int n_in,
                              void* d_out, int out_size)
{
    const float* input_feat  = (const float*)d_in[0];
    const float* rho_coords  = (const float*)d_in[1];
    const float* theta_coord = (const float*)d_in[2];
    const float* mask        = (const float*)d_in[3];
    const float* mu_rho      = (const float*)d_in[4];
    const float* sigma_rho   = (const float*)d_in[5];
    const float* mu_theta    = (const float*)d_in[6];
    const float* sigma_theta = (const float*)d_in[7];
    const float* W_conv      = (const float*)d_in[8];
    const float* b_conv      = (const float*)d_in[9];
    const float* fcc_w       = (const float*)d_in[10];
    const float* fcc_b       = (const float*)d_in[11];
    float* out = (float*)d_out;

    k1_gauss<<<(S_N * V_N + 255) / 256, 256>>>(input_feat, rho_coords, theta_coord,
                                               mask, mu_rho, sigma_rho,
                                               mu_theta, sigma_theta);
    k2_gemm<<<S_N, 256>>>();
    k3_conv<<<S_N, 400>>>(W_conv, b_conv);
    k4_fcc<<<S_N, 80>>>(fcc_w, fcc_b, out);
    k5_loss<<<1, 128>>>(out);
}

// round 2
// speedup vs baseline: 1.9188x; 1.9188x over previous
#include <cuda_runtime.h>
#include <math.h>

// Problem constants
#define S_N   256
#define V_N   200
#define F_N   5
#define G_N   80
#define NT    16     // thetas
#define NR    5      // rhos
#define NROT  16
#define EPSF  1e-5f

#define TWO_PI_F 6.28318530717958647692f
#define DTH_F    0.39269908169872415481f   // 2*pi/16 (rounds to same f32 as jax)
#define LOG2E_F  1.44269504088896340736f

// Scratch: normalized gaussian descriptors, layout [s][r][g=p*16+k][8] (f 0..4 + pad)
__device__ float d_GDN[(size_t)S_N * NROT * G_N * 8];   // 10.5 MB

// ---------------- packed f32x2 helpers (Blackwell FFMA2) ----------------
__device__ __forceinline__ unsigned long long ffma2(unsigned long long a,
                                                    unsigned long long b,
                                                    unsigned long long c) {
    unsigned long long d;
    asm("fma.rn.f32x2 %0, %1, %2, %3;" : "=l"(d) : "l"(a), "l"(b), "l"(c));
    return d;
}
__device__ __forceinline__ unsigned long long pack2(float x) {
    unsigned long long d;
    asm("mov.b64 %0, {%1, %1};" : "=l"(d) : "f"(x));
    return d;
}
__device__ __forceinline__ float2 unpack2(unsigned long long v) {
    float2 f;
    asm("mov.b64 {%0, %1}, %2;" : "=f"(f.x), "=f"(f.y) : "l"(v));
    return f;
}
__device__ __forceinline__ float ex2f(float x) {
    float r;
    asm("ex2.approx.f32 %0, %1;" : "=f"(r) : "f"(x));
    return r;
}

// ---------------------------------------------------------------------------
// Kernel 12 (fused k1+k2): one block per s, 256 threads = (r,k).
// Stage A[v][32] (rg*mask*{1,feat}) + theta[v] in smem; main loop recomputes
// the angular gaussian tg on the fly per (thread, v) and accumulates the
// 32-wide GEMM row with packed FFMA2. Epilogue normalizes and writes GDN.
// ---------------------------------------------------------------------------
__global__ void k12_gauss_gemm(const float* __restrict__ feat,
                               const float* __restrict__ rho,
                               const float* __restrict__ theta,
                               const float* __restrict__ mask,
                               const float* __restrict__ mu_rho,
                               const float* __restrict__ sigma_rho,
                               const float* __restrict__ mu_theta,
                               const float* __restrict__ sigma_theta)
{
    __shared__ float As[V_N * 32];   // 25.6 KB, rows 16B-aligned
    __shared__ float t_s[V_N];

    int s   = blockIdx.x;
    int tid = threadIdx.x;
    int r   = tid >> 4;
    int k   = tid & 15;

    // per-thread theta-gaussian constants
    float mu_k = mu_theta[k];                    // row f=0 (all rows identical)
    float st   = sigma_theta[k];
    float isLk = -LOG2E_F / (st * st + EPSF);    // fold log2e, negate
    float rdel = (float)r * DTH_F;

    // ---- stage A ----
    if (tid < V_N) {
        int v = tid;
        int idx = s * V_N + v;
        float rh = rho[idx];
        float m  = mask[idx];
        t_s[v]   = theta[idx];
        float fv[5];
#pragma unroll
        for (int f = 0; f < 5; f++) fv[f] = feat[idx * 5 + f];
#pragma unroll
        for (int p = 0; p < NR; p++) {
            float mr = mu_rho[p * 16];
            float sr = sigma_rho[p * 16];
            float d  = rh - mr;
            float rg = ex2f(-(d * d) * (LOG2E_F / (sr * sr + EPSF)));
            float rm = rg * m;
            As[v * 32 + p * 6] = rm;
#pragma unroll
            for (int f = 0; f < 5; f++) As[v * 32 + p * 6 + 1 + f] = rm * fv[f];
        }
        As[v * 32 + 30] = 0.0f;
        As[v * 32 + 31] = 0.0f;
    }
    __syncthreads();

    // ---- main GEMM loop: acc[16] f32x2 pairs = 32 floats ----
    unsigned long long acc[16];
#pragma unroll
    for (int j = 0; j < 16; j++) acc[j] = 0ull;

#pragma unroll 2
    for (int v = 0; v < V_N; v++) {
        float tv = t_s[v];
        float tr = tv + rdel;
        tr = (tr >= TWO_PI_F) ? (tr - TWO_PI_F) : tr;
        float dd  = tr - mu_k;
        float tg  = ex2f(dd * dd * isLk);
        unsigned long long tg2 = pack2(tg);
        const ulonglong2* av = (const ulonglong2*)&As[v * 32];
#pragma unroll
        for (int j = 0; j < 8; j++) {
            ulonglong2 q = av[j];
            acc[2 * j + 0] = ffma2(tg2, q.x, acc[2 * j + 0]);
            acc[2 * j + 1] = ffma2(tg2, q.y, acc[2 * j + 1]);
        }
    }

    // ---- normalize + write: pairs (p*3+0)=(den,f0), +1=(f1,f2), +2=(f3,f4) ----
    float* gbase = d_GDN + (((size_t)s * NROT + r) * G_N + k) * 8;
#pragma unroll
    for (int p = 0; p < NR; p++) {
        float2 q0 = unpack2(acc[p * 3 + 0]);
        float2 q1 = unpack2(acc[p * 3 + 1]);
        float2 q2 = unpack2(acc[p * 3 + 2]);
        float inv = 1.0f / (q0.x + EPSF);
        float4 o0 = make_float4(q0.y * inv, q1.x * inv, q1.y * inv, q2.x * inv);
        float4 o1 = make_float4(q2.y * inv, 0.0f, 0.0f, 0.0f);
        float4* po = (float4*)(gbase + (size_t)p * 16 * 8);
        po[0] = o0;
        po[1] = o1;
    }
}

// ---------------------------------------------------------------------------
// Kernel 34 (fused k3+k4): one block per s, 320 threads = (rgroup 0..3, gp 0..79).
// 2 passes of 8 rotations staged in smem; each thread computes 5 f-dots per
// rotation reusing a single W load per g. Then max-reduce over rotations,
// bias+relu, and the fcc GEMV epilogue.
// ---------------------------------------------------------------------------
__global__ void k34_conv_fcc(const float* __restrict__ Wc,
                             const float* __restrict__ bc,
                             const float* __restrict__ fw,
                             const float* __restrict__ fb,
                             float* __restrict__ out)
{
    __shared__ float Wsh[G_N * G_N];          // 25.6 KB
    __shared__ float gsh[8 * G_N * 8];        // 20.5 KB (also reused for red/drow/part)

    int s   = blockIdx.x;
    int tid = threadIdx.x;          // 0..319
    int rg  = tid / 80;             // rotation group
    int gp  = tid % 80;             // output g'

    for (int i = tid; i < G_N * G_N; i += 320) Wsh[i] = Wc[i];

    float mx0 = -1e30f, mx1 = -1e30f, mx2 = -1e30f, mx3 = -1e30f, mx4 = -1e30f;

#pragma unroll
    for (int pass = 0; pass < 2; pass++) {
        __syncthreads();   // also orders Wsh fill before first use
        // stage 8 rotations: contiguous 5120 floats
        const float4* src = (const float4*)(d_GDN + ((size_t)s * NROT + pass * 8) * G_N * 8);
        float4* dst = (float4*)gsh;
        for (int i = tid; i < 8 * G_N * 2; i += 320) dst[i] = src[i];
        __syncthreads();

#pragma unroll
        for (int r2 = 0; r2 < 2; r2++) {
            const float* grow = &gsh[(rg * 2 + r2) * G_N * 8];
            float d0 = 0.f, d1 = 0.f, d2 = 0.f, d3 = 0.f, d4 = 0.f;
#pragma unroll 4
            for (int g = 0; g < G_N; g++) {
                float w = Wsh[g * 80 + gp];
                float4 a = *(const float4*)&grow[g * 8];
                float  b = grow[g * 8 + 4];
                d0 += a.x * w; d1 += a.y * w; d2 += a.z * w; d3 += a.w * w; d4 += b * w;
            }
            mx0 = fmaxf(mx0, d0); mx1 = fmaxf(mx1, d1); mx2 = fmaxf(mx2, d2);
            mx3 = fmaxf(mx3, d3); mx4 = fmaxf(mx4, d4);
        }
    }

    // ---- reduce max over the 4 rotation groups ----
    __syncthreads();
    float* red  = gsh;          // 4*400 = 1600
    float* drow = gsh + 1600;   // 400
    float* part = gsh + 2000;   // 320
    red[rg * 400 + 0 * 80 + gp] = mx0;
    red[rg * 400 + 1 * 80 + gp] = mx1;
    red[rg * 400 + 2 * 80 + gp] = mx2;
    red[rg * 400 + 3 * 80 + gp] = mx3;
    red[rg * 400 + 4 * 80 + gp] = mx4;
    __syncthreads();

    // desc[j] = relu(max_r + bias)
    {
        int j = tid;   // 0..319
        float v = fmaxf(fmaxf(red[j], red[400 + j]), fmaxf(red[800 + j], red[1200 + j]));
        drow[j] = fmaxf(v + bc[j], 0.0f);
        if (tid < 80) {
            int j2 = 320 + tid;
            float v2 = fmaxf(fmaxf(red[j2], red[400 + j2]), fmaxf(red[800 + j2], red[1200 + j2]));
            drow[j2] = fmaxf(v2 + bc[j2], 0.0f);
        }
    }
    __syncthreads();

    // ---- fcc: out[s][g] = fb[g] + sum_j drow[j]*fw[j][g], split j in 4 chunks ----
    {
        int c = tid / 80;      // chunk
        int g = tid % 80;
        const float* fwp = fw + (size_t)(c * 100) * 80 + g;
        float acc = 0.0f;
#pragma unroll 10
        for (int jj = 0; jj < 100; jj++)
            acc += drow[c * 100 + jj] * fwp[jj * 80];
        part[tid] = acc;
    }
    __syncthreads();
    if (tid < 80) {
        out[(size_t)s * 80 + tid] = fb[tid] + part[tid] + part[80 + tid]
                                  + part[160 + tid] + part[240 + tid];
    }
}

// ---------------------------------------------------------------------------
// Kernel 5: pairwise distances, score, data_loss. One block, 128 threads.
// out layout: [0:20480) global_desc, [20480] data_loss, [20481:20609) score
// ---------------------------------------------------------------------------
__global__ void k5_loss(float* __restrict__ out)
{
    int tid = threadIdx.x;  // 0..127
    const float* gd = out;
    int i = tid & 63;
    const float *xa, *xb;
    if (tid < 64) { xa = gd + (size_t)(64 + i) * 80;  xb = gd + (size_t)i * 80; }
    else          { xa = gd + (size_t)(128 + i) * 80; xb = gd + (size_t)(192 + i) * 80; }

    float d = 0.0f;
#pragma unroll 8
    for (int j = 0; j < 80; j++) {
        float df = xa[j] - xb[j];
        d += df * df;
    }
    out[20481 + tid] = d;                       // score

    __shared__ float sd[128];
    float rv = (tid < 64) ? fmaxf(d - 0.0f, 0.0f)     // pos_r
                          : fmaxf(10.0f - d, 0.0f);   // neg_r
    sd[tid] = rv;
    __syncthreads();

    if (tid == 0) {
        float mp = 0.0f, mn = 0.0f;
        for (int j = 0; j < 64; j++) { mp += sd[j]; mn += sd[64 + j]; }
        mp *= (1.0f / 64.0f); mn *= (1.0f / 64.0f);
        float vp = 0.0f, vn = 0.0f;
        for (int j = 0; j < 64; j++) {
            float a = sd[j]      - mp; vp += a * a;
            float c = sd[64 + j] - mn; vn += c * c;
        }
        out[20480] = sqrtf(vp / 63.0f) + sqrtf(vn / 63.0f) + mp + mn;
    }
}

// ---------------------------------------------------------------------------
extern "C" void kernel_launch(void* const* d_in, const int* in_sizes, int n_in,
                              void* d_out, int out_size)
{
    const float* input_feat  = (const float*)d_in[0];
    const float* rho_coords  = (const float*)d_in[1];
    const float* theta_coord = (const float*)d_in[2];
    const float* mask        = (const float*)d_in[3];
    const float* mu_rho      = (const float*)d_in[4];
    const float* sigma_rho   = (const float*)d_in[5];
    const float* mu_theta    = (const float*)d_in[6];
    const float* sigma_theta = (const float*)d_in[7];
    const float* W_conv      = (const float*)d_in[8];
    const float* b_conv      = (const float*)d_in[9];
    const float* fcc_w       = (const float*)d_in[10];
    const float* fcc_b       = (const float*)d_in[11];
    float* out = (float*)d_out;

    k12_gauss_gemm<<<S_N, 256>>>(input_feat, rho_coords, theta_coord, mask,
                                 mu_rho, sigma_rho, mu_theta, sigma_theta);
    k34_conv_fcc<<<S_N, 320>>>(W_conv, b_conv, fcc_w, fcc_b, out);
    k5_loss<<<1, 128>>>(out);
}